// round 9
// baseline (speedup 1.0000x reference)
#include <cuda_runtime.h>

#define NN   50000
#define EE   800000
#define IND  128
#define OUTD 64
#define EDD  32

// ---------------- scratch (static device arrays; no allocation) ----------------
__device__ __align__(16) float g_z[NN * OUTD];     // z = x@W_fc + b_fc
__device__ float g_asrc[NN];                       // z . Wa[0:64]
__device__ float g_adst[NN];                       // z . Wa[64:128]
__device__ float g_denom[NN];                      // softmax denominator per dst
__device__ float g_p[EE];                          // exp(leaky(logit)) per edge
__device__ float g_g[NN * EDD];                    // sum_e alpha * edge_attr per dst

// ---------------- helpers ----------------
__device__ __forceinline__ unsigned long long bcast2(float x) {
    unsigned long long r;
    asm("mov.b64 %0, {%1, %1};" : "=l"(r) : "f"(x));
    return r;
}
__device__ __forceinline__ unsigned long long pack2f(float2 v) {
    unsigned long long r;
    asm("mov.b64 %0, {%1, %2};" : "=l"(r) : "f"(v.x), "f"(v.y));
    return r;
}
__device__ __forceinline__ float2 unpack2(unsigned long long v) {
    float2 r;
    asm("mov.b64 {%0, %1}, %2;" : "=f"(r.x), "=f"(r.y) : "l"(v));
    return r;
}
// packed f32x2 fma: acc = a*b + acc (2 fp32 lanes per instruction)
__device__ __forceinline__ void fma2(unsigned long long& acc,
                                     unsigned long long a, unsigned long long b) {
    asm("fma.rn.f32x2 %0, %1, %2, %0;" : "+l"(acc) : "l"(a), "l"(b));
}
__device__ __forceinline__ float wredsum(float v) {
#pragma unroll
    for (int o = 16; o > 0; o >>= 1) v += __shfl_xor_sync(0xffffffffu, v, o);
    return v;
}

// ---------------- K1: node transforms ----------------
// z = x@W_fc + b_fc ; out = x@W_self + b_self ; a_src/a_dst node scalars.
// Also zeroes g_denom and g_g for this launch.
// One warp handles 2 nodes per iteration; lane owns output channels (2l, 2l+1).
__global__ void k1_node(const float* __restrict__ x,
                        const float* __restrict__ Wfc,  const float* __restrict__ bfc,
                        const float* __restrict__ Wself, const float* __restrict__ bself,
                        const float* __restrict__ Wattn,
                        float* __restrict__ out)
{
    extern __shared__ float sm[];
    float* sWfc = sm;                     // 128*64
    float* sWs  = sm + IND * OUTD;        // 128*64
    float* sx   = sm + 2 * IND * OUTD;    // 8 warps * 256
    const int tid = threadIdx.x;

    // zero per-launch scratch (kernel-boundary orders this before K2/K3)
    {
        int gt = blockIdx.x * blockDim.x + tid;
        int gs = gridDim.x * blockDim.x;
        for (int i = gt; i < NN * EDD; i += gs) g_g[i] = 0.f;
        for (int i = gt; i < NN; i += gs) g_denom[i] = 0.f;
    }
    // stage weights
    for (int i = tid; i < (IND * OUTD) / 4; i += blockDim.x) {
        ((float4*)sWfc)[i] = ((const float4*)Wfc)[i];
        ((float4*)sWs)[i]  = ((const float4*)Wself)[i];
    }
    __syncthreads();

    const int warp = tid >> 5, lane = tid & 31;
    const int gw = blockIdx.x * 8 + warp, nw = gridDim.x * 8;
    float* sx0 = sx + warp * 256;
    float* sx1 = sx0 + 128;

    const unsigned long long bfp = pack2f(((const float2*)bfc)[lane]);
    const unsigned long long bsp = pack2f(((const float2*)bself)[lane]);
    const float wa_s0 = Wattn[2 * lane],        wa_s1 = Wattn[2 * lane + 1];
    const float wa_d0 = Wattn[OUTD + 2 * lane], wa_d1 = Wattn[OUTD + 2 * lane + 1];

    for (int n0 = gw * 2; n0 < NN; n0 += nw * 2) {
        const int n1 = n0 + 1;   // NN even, n0 even -> n1 always valid
        ((float4*)sx0)[lane] = ((const float4*)(x + (size_t)n0 * IND))[lane];
        ((float4*)sx1)[lane] = ((const float4*)(x + (size_t)n1 * IND))[lane];
        __syncwarp();

        unsigned long long aF0 = bfp, aF1 = bfp, aS0 = bsp, aS1 = bsp;
#pragma unroll 16
        for (int d = 0; d < IND; d++) {
            unsigned long long x0 = bcast2(sx0[d]);
            unsigned long long x1 = bcast2(sx1[d]);
            unsigned long long wf = ((const unsigned long long*)(sWfc + d * OUTD))[lane];
            unsigned long long ws = ((const unsigned long long*)(sWs  + d * OUTD))[lane];
            fma2(aF0, x0, wf); fma2(aF1, x1, wf);
            fma2(aS0, x0, ws); fma2(aS1, x1, ws);
        }

        float2 z0 = unpack2(aF0), z1 = unpack2(aF1);
        ((float2*)(g_z + (size_t)n0 * OUTD))[lane] = z0;
        ((float2*)(g_z + (size_t)n1 * OUTD))[lane] = z1;
        ((float2*)(out + (size_t)n0 * OUTD))[lane] = unpack2(aS0);
        ((float2*)(out + (size_t)n1 * OUTD))[lane] = unpack2(aS1);

        float ps0 = wredsum(z0.x * wa_s0 + z0.y * wa_s1);
        float pd0 = wredsum(z0.x * wa_d0 + z0.y * wa_d1);
        float ps1 = wredsum(z1.x * wa_s0 + z1.y * wa_s1);
        float pd1 = wredsum(z1.x * wa_d0 + z1.y * wa_d1);
        if (lane == 0) {
            g_asrc[n0] = ps0; g_adst[n0] = pd0;
            g_asrc[n1] = ps1; g_adst[n1] = pd1;
        }
        __syncwarp();
    }
}

// ---------------- K2: edge logits + softmax denominator ----------------
// 8 lanes per edge: 32-dot of edge_attr with Wa[128:160], then
// p = exp(leaky_relu(a_src[row] + a_dst[col] + dot + b)); denom[col] += p.
__global__ void k2_logits(const float* __restrict__ ea, const int* __restrict__ eidx,
                          const float* __restrict__ Wattn, const float* __restrict__ battn)
{
    int g = blockIdx.x * blockDim.x + threadIdx.x;
    int e = g >> 3, sl = g & 7;
    if (e >= EE) return;
    float4 v = ((const float4*)(ea + (size_t)e * EDD))[sl];
    float4 w = ((const float4*)(Wattn + 2 * OUTD))[sl];
    float s = v.x * w.x + v.y * w.y + v.z * w.z + v.w * w.w;
    s += __shfl_xor_sync(0xffffffffu, s, 4);
    s += __shfl_xor_sync(0xffffffffu, s, 2);
    s += __shfl_xor_sync(0xffffffffu, s, 1);
    if (sl == 0) {
        int row = eidx[e], col = eidx[EE + e];
        float logit = g_asrc[row] + g_adst[col] + s + battn[0];
        float lr = logit > 0.f ? logit : 0.2f * logit;
        float pe = __expf(lr);    // logits bounded ~|6|: no overflow, max-shift elided
        g_p[e] = pe;
        atomicAdd(&g_denom[col], pe);
    }
}

// ---------------- K3: attention-weighted scatter ----------------
// Per edge (1 warp): alpha = p/denom[col];
//   out[col] += alpha * z[row]          (64 floats)
//   g[col]   += alpha * edge_attr[e]    (32 floats; edge transform factored out)
__global__ void k3_scatter(const float* __restrict__ ea, const int* __restrict__ eidx,
                           float* __restrict__ out)
{
    int e = (blockIdx.x * blockDim.x + threadIdx.x) >> 5;
    int lane = threadIdx.x & 31;
    if (e >= EE) return;
    float eav = ea[(size_t)e * EDD + lane];
    int row = eidx[e], col = eidx[EE + e];
    float alpha = g_p[e] / fmaxf(g_denom[col], 1e-16f);

    float2 zr = ((const float2*)(g_z + (size_t)row * OUTD))[lane];
    float* op = out + (size_t)col * OUTD + 2 * lane;
    atomicAdd(op,     alpha * zr.x);
    atomicAdd(op + 1, alpha * zr.y);

    float e0 = __shfl_sync(0xffffffffu, eav, (2 * lane) & 31);
    float e1 = __shfl_sync(0xffffffffu, eav, (2 * lane + 1) & 31);
    if (lane < 16) {
        float* gp = g_g + (size_t)col * EDD + 2 * lane;
        atomicAdd(gp,     alpha * e0);
        atomicAdd(gp + 1, alpha * e1);
    }
}

// ---------------- K4: factored edge-transform epilogue ----------------
// out[n] += g[n] @ W_edge + (deg_in(n)>0 ? b_edge : 0)   (Σ alpha = 1 per node)
__global__ void k4_edgegemm(const float* __restrict__ We, const float* __restrict__ be,
                            float* __restrict__ out)
{
    __shared__ __align__(16) float sWe[EDD * OUTD];
    __shared__ float sbe[OUTD];
    int tid = threadIdx.x;
    for (int i = tid; i < (EDD * OUTD) / 4; i += blockDim.x)
        ((float4*)sWe)[i] = ((const float4*)We)[i];
    if (tid < OUTD) sbe[tid] = be[tid];
    __syncthreads();

    int warp = tid >> 5, lane = tid & 31;
    int gw = blockIdx.x * 8 + warp, nw = gridDim.x * 8;
    for (int n = gw; n < NN; n += nw) {
        float gv = g_g[(size_t)n * EDD + lane];
        float acc0 = 0.f, acc1 = 0.f;
#pragma unroll
        for (int d = 0; d < EDD; d++) {
            float gd = __shfl_sync(0xffffffffu, gv, d);
            float2 w = ((const float2*)(sWe + d * OUTD))[lane];
            acc0 = fmaf(gd, w.x, acc0);
            acc1 = fmaf(gd, w.y, acc1);
        }
        if (g_denom[n] > 0.f) { acc0 += sbe[2 * lane]; acc1 += sbe[2 * lane + 1]; }
        float2* op = (float2*)(out + (size_t)n * OUTD) + lane;
        float2 o = *op;
        o.x += acc0; o.y += acc1;
        *op = o;
    }
}

// ---------------- launch ----------------
extern "C" void kernel_launch(void* const* d_in, const int* in_sizes, int n_in,
                              void* d_out, int out_size)
{
    const float* x     = (const float*)d_in[0];
    const float* ea    = (const float*)d_in[1];
    const int*   eidx  = (const int*)  d_in[2];
    const float* Wfc   = (const float*)d_in[3];
    const float* bfc   = (const float*)d_in[4];
    const float* Wattn = (const float*)d_in[5];
    const float* battn = (const float*)d_in[6];
    const float* Wedge = (const float*)d_in[7];
    const float* bedge = (const float*)d_in[8];
    const float* Wself = (const float*)d_in[9];
    const float* bself = (const float*)d_in[10];
    float* out = (float*)d_out;

    const size_t smem1 = (2 * IND * OUTD + 8 * 256) * sizeof(float);  // 73728 B
    cudaFuncSetAttribute(k1_node, cudaFuncAttributeMaxDynamicSharedMemorySize, (int)smem1);

    k1_node<<<296, 256, smem1>>>(x, Wfc, bfc, Wself, bself, Wattn, out);
    k2_logits<<<(EE * 8) / 256, 256>>>(ea, eidx, Wattn, battn);
    k3_scatter<<<(EE * 32) / 256, 256>>>(ea, eidx, out);
    k4_edgegemm<<<296, 256>>>(Wedge, bedge, out);
}

// round 11
// speedup vs baseline: 1.1222x; 1.1222x over previous
#include <cuda_runtime.h>

#define NN   50000
#define EE   800000
#define IND  128
#define OUTD 64
#define EDD  32

typedef unsigned long long ull;

// ---------------- scratch (static device arrays; no allocation) ----------------
__device__ __align__(16) float g_z[NN * OUTD];     // z = x@W_fc + b_fc
__device__ float g_asrc[NN];                       // z . Wa[0:64]
__device__ float g_adst[NN];                       // z . Wa[64:128]
__device__ float g_denom[NN];                      // sum_e p  per dst
__device__ __align__(16) float g_sz[NN * OUTD];    // sum_e p * z[row]  per dst
__device__ __align__(16) float g_sg[NN * EDD];     // sum_e p * edge_attr per dst

// ---------------- helpers ----------------
__device__ __forceinline__ ull bcast2(float x) {
    ull r; asm("mov.b64 %0, {%1, %1};" : "=l"(r) : "f"(x)); return r;
}
__device__ __forceinline__ ull pack2f(float2 v) {
    ull r; asm("mov.b64 %0, {%1, %2};" : "=l"(r) : "f"(v.x), "f"(v.y)); return r;
}
__device__ __forceinline__ float2 unpack2(ull v) {
    float2 r; asm("mov.b64 {%0, %1}, %2;" : "=f"(r.x), "=f"(r.y) : "l"(v)); return r;
}
// packed f32x2 fma: acc = a*b + acc (2 fp32 lanes per instruction)
__device__ __forceinline__ void fma2(ull& acc, ull a, ull b) {
    asm("fma.rn.f32x2 %0, %1, %2, %0;" : "+l"(acc) : "l"(a), "l"(b));
}
__device__ __forceinline__ float wredsum(float v) {
#pragma unroll
    for (int o = 16; o > 0; o >>= 1) v += __shfl_xor_sync(0xffffffffu, v, o);
    return v;
}
__device__ __forceinline__ void red_v4(float* p, float a, float b, float c, float d) {
    asm volatile("red.global.add.v4.f32 [%0], {%1,%2,%3,%4};"
                 :: "l"(p), "f"(a), "f"(b), "f"(c), "f"(d) : "memory");
}
__device__ __forceinline__ void red_f32(float* p, float v) {
    asm volatile("red.global.add.f32 [%0], %1;" :: "l"(p), "f"(v) : "memory");
}

// ---------------- K1: node transforms (4 nodes / warp / iter) ----------------
// z = x@W_fc + b_fc ; out = x@W_self + b_self ; a_src/a_dst node scalars.
// Also zeroes g_denom, g_sz, g_sg for this launch.
__global__ void __launch_bounds__(256, 2)
k1_node(const float* __restrict__ x,
        const float* __restrict__ Wfc,   const float* __restrict__ bfc,
        const float* __restrict__ Wself, const float* __restrict__ bself,
        const float* __restrict__ Wattn,
        float* __restrict__ out)
{
    extern __shared__ float sm[];
    float* sWfc = sm;                     // 128*64
    float* sWs  = sm + IND * OUTD;        // 128*64
    float* sx   = sm + 2 * IND * OUTD;    // 8 warps * 4 * 128
    const int tid = threadIdx.x;

    // zero per-launch scratch (kernel-boundary orders this before K2/K3)
    {
        int gt = blockIdx.x * blockDim.x + tid;
        int gs = gridDim.x * blockDim.x;
        float4 z4 = make_float4(0.f, 0.f, 0.f, 0.f);
        for (int i = gt; i < (NN * OUTD) / 4; i += gs) ((float4*)g_sz)[i] = z4;
        for (int i = gt; i < (NN * EDD) / 4;  i += gs) ((float4*)g_sg)[i] = z4;
        for (int i = gt; i < NN / 4;          i += gs) ((float4*)g_denom)[i] = z4;
    }
    // stage weights
    for (int i = tid; i < (IND * OUTD) / 4; i += blockDim.x) {
        ((float4*)sWfc)[i] = ((const float4*)Wfc)[i];
        ((float4*)sWs)[i]  = ((const float4*)Wself)[i];
    }
    __syncthreads();

    const int warp = tid >> 5, lane = tid & 31;
    const int gw = blockIdx.x * 8 + warp, nw = gridDim.x * 8;
    float* sxw = sx + warp * 512;

    const ull bfp = pack2f(((const float2*)bfc)[lane]);
    const ull bsp = pack2f(((const float2*)bself)[lane]);
    const float wa_s0 = Wattn[2 * lane],        wa_s1 = Wattn[2 * lane + 1];
    const float wa_d0 = Wattn[OUTD + 2 * lane], wa_d1 = Wattn[OUTD + 2 * lane + 1];

    for (int n0 = gw * 4; n0 < NN; n0 += nw * 4) {      // 50000 % 4 == 0
#pragma unroll
        for (int k = 0; k < 4; k++)
            ((float4*)(sxw + k * IND))[lane] =
                ((const float4*)(x + (size_t)(n0 + k) * IND))[lane];
        __syncwarp();

        ull aF[4] = {bfp, bfp, bfp, bfp};
        ull aS[4] = {bsp, bsp, bsp, bsp};
#pragma unroll 4
        for (int d = 0; d < IND; d++) {
            ull wf = ((const ull*)(sWfc + d * OUTD))[lane];
            ull ws = ((const ull*)(sWs  + d * OUTD))[lane];
#pragma unroll
            for (int k = 0; k < 4; k++) {
                ull xv = bcast2(sxw[k * IND + d]);
                fma2(aF[k], xv, wf);
                fma2(aS[k], xv, ws);
            }
        }
#pragma unroll
        for (int k = 0; k < 4; k++) {
            float2 z = unpack2(aF[k]);
            ((float2*)(g_z + (size_t)(n0 + k) * OUTD))[lane] = z;
            ((float2*)(out + (size_t)(n0 + k) * OUTD))[lane] = unpack2(aS[k]);
            float ps = wredsum(z.x * wa_s0 + z.y * wa_s1);
            float pd = wredsum(z.x * wa_d0 + z.y * wa_d1);
            if (lane == 0) { g_asrc[n0 + k] = ps; g_adst[n0 + k] = pd; }
        }
        __syncwarp();
    }
}

// ---------------- K2: fused edge pass (16 lanes / edge, 2 edges / warp) ----------------
// p = exp(leaky(a_src[row] + a_dst[col] + ea.Wa_e + b)); then UNNORMALIZED scatters:
//   denom[col]  += p                 (1  scalar red)
//   S_z[col]    += p * z[row]        (16 red.v4)
//   S_g[col]    += p * edge_attr     ( 8 red.v4)
// Normalization and the factored edge transform happen in K3.
__global__ void k2_edge(const float* __restrict__ ea, const int* __restrict__ eidx,
                        const float* __restrict__ Wattn, const float* __restrict__ battn)
{
    int gt = blockIdx.x * blockDim.x + threadIdx.x;
    int e  = gt >> 4;           // grid sized exactly: e < EE always
    int hl = gt & 15;

    int row = __ldg(eidx + e);
    int col = __ldg(eidx + EE + e);

    // 32-dot of edge_attr with Wa[128:160]; two redundant 8-lane copies per edge
    float4 ev = ((const float4*)(ea + (size_t)e * EDD))[hl & 7];
    float4 w  = __ldg((const float4*)(Wattn + 2 * OUTD) + (hl & 7));
    float s = ev.x * w.x + ev.y * w.y + ev.z * w.z + ev.w * w.w;
    s += __shfl_xor_sync(0xffffffffu, s, 4);
    s += __shfl_xor_sync(0xffffffffu, s, 2);
    s += __shfl_xor_sync(0xffffffffu, s, 1);

    float logit = g_asrc[row] + g_adst[col] + s + battn[0];
    float lr = logit > 0.f ? logit : 0.2f * logit;
    float p  = __expf(lr);      // logits bounded ~|6|: max-shift elided, alpha unchanged

    // z message: 16 lanes * float4 = 64 channels
    float4 z = ((const float4*)(g_z + (size_t)row * OUTD))[hl];
    red_v4(g_sz + (size_t)col * OUTD + hl * 4, p * z.x, p * z.y, p * z.z, p * z.w);

    if (hl < 8)
        red_v4(g_sg + (size_t)col * EDD + hl * 4, p * ev.x, p * ev.y, p * ev.z, p * ev.w);
    if (hl == 0)
        red_f32(g_denom + col, p);
}

// ---------------- K3: node epilogue ----------------
// out[n] += (S_z[n] + S_g[n]@W_edge) / max(denom,1e-16) + (denom>0 ? b_edge : 0)
__global__ void k3_final(const float* __restrict__ We, const float* __restrict__ be,
                         float* __restrict__ out)
{
    __shared__ __align__(16) float sWe[EDD * OUTD];
    __shared__ float sbe[OUTD];
    int tid = threadIdx.x;
    for (int i = tid; i < (EDD * OUTD) / 4; i += blockDim.x)
        ((float4*)sWe)[i] = ((const float4*)We)[i];
    if (tid < OUTD) sbe[tid] = be[tid];
    __syncthreads();

    int warp = tid >> 5, lane = tid & 31;
    int gw = blockIdx.x * 8 + warp, nw = gridDim.x * 8;
    for (int n = gw; n < NN; n += nw) {
        float gv    = g_sg[(size_t)n * EDD + lane];
        float denom = g_denom[n];
        float2 sz   = ((const float2*)(g_sz + (size_t)n * OUTD))[lane];
        float acc0 = 0.f, acc1 = 0.f;
#pragma unroll
        for (int d = 0; d < EDD; d++) {
            float gd = __shfl_sync(0xffffffffu, gv, d);
            float2 wv = ((const float2*)(sWe + d * OUTD))[lane];
            acc0 = fmaf(gd, wv.x, acc0);
            acc1 = fmaf(gd, wv.y, acc1);
        }
        float inv  = 1.f / fmaxf(denom, 1e-16f);
        float add0 = (sz.x + acc0) * inv;
        float add1 = (sz.y + acc1) * inv;
        if (denom > 0.f) { add0 += sbe[2 * lane]; add1 += sbe[2 * lane + 1]; }
        float2* op = (float2*)(out + (size_t)n * OUTD) + lane;
        float2 o = *op;
        o.x += add0; o.y += add1;
        *op = o;
    }
}

// ---------------- launch ----------------
extern "C" void kernel_launch(void* const* d_in, const int* in_sizes, int n_in,
                              void* d_out, int out_size)
{
    const float* x     = (const float*)d_in[0];
    const float* ea    = (const float*)d_in[1];
    const int*   eidx  = (const int*)  d_in[2];
    const float* Wfc   = (const float*)d_in[3];
    const float* bfc   = (const float*)d_in[4];
    const float* Wattn = (const float*)d_in[5];
    const float* battn = (const float*)d_in[6];
    const float* Wedge = (const float*)d_in[7];
    const float* bedge = (const float*)d_in[8];
    const float* Wself = (const float*)d_in[9];
    const float* bself = (const float*)d_in[10];
    float* out = (float*)d_out;

    const size_t smem1 = (2 * IND * OUTD + 8 * 512) * sizeof(float);  // 81920 B
    cudaFuncSetAttribute(k1_node, cudaFuncAttributeMaxDynamicSharedMemorySize, (int)smem1);

    k1_node<<<296, 256, smem1>>>(x, Wfc, bfc, Wself, bself, Wattn, out);
    k2_edge<<<(EE * 16) / 256, 256>>>(ea, eidx, Wattn, battn);   // 50000 blocks, exact
    k3_final<<<1184, 256>>>(Wedge, bedge, out);
}

// round 12
// speedup vs baseline: 1.3038x; 1.1618x over previous
#include <cuda_runtime.h>

#define NN   50000
#define EE   800000
#define IND  128
#define OUTD 64
#define EDD  32

typedef unsigned long long ull;

// ---------------- scratch (static device arrays; no allocation) ----------------
__device__ __align__(16) float g_z[NN * OUTD];     // z = x@W_fc + b_fc
__device__ float g_asrc[NN];                       // z . Wa[0:64]
__device__ float g_adst[NN];                       // z . Wa[64:128]
__device__ int   g_deg[NN];                        // in-degree per dst
__device__ int   g_start[NN];                      // CSR start offsets
__device__ int   g_cursor[NN];                     // fill cursor per dst
__device__ __align__(16) float4 g_pack[EE];        // {p, row, e, -} per CSR slot

// ---------------- helpers ----------------
__device__ __forceinline__ ull bcast2(float x) {
    ull r; asm("mov.b64 %0, {%1, %1};" : "=l"(r) : "f"(x)); return r;
}
__device__ __forceinline__ ull pack2f(float2 v) {
    ull r; asm("mov.b64 %0, {%1, %2};" : "=l"(r) : "f"(v.x), "f"(v.y)); return r;
}
__device__ __forceinline__ float2 unpack2(ull v) {
    float2 r; asm("mov.b64 {%0, %1}, %2;" : "=f"(r.x), "=f"(r.y) : "l"(v)); return r;
}
// packed f32x2 fma: acc = a*b + acc (2 fp32 lanes per instruction)
__device__ __forceinline__ void fma2(ull& acc, ull a, ull b) {
    asm("fma.rn.f32x2 %0, %1, %2, %0;" : "+l"(acc) : "l"(a), "l"(b));
}
__device__ __forceinline__ float wredsum(float v) {
#pragma unroll
    for (int o = 16; o > 0; o >>= 1) v += __shfl_xor_sync(0xffffffffu, v, o);
    return v;
}

// ---------------- K1: node transforms (8 nodes / warp / iter) ----------------
// z = x@W_fc + b_fc ; out = x@W_self + b_self ; a_src/a_dst node scalars.
// Also zeroes g_deg for this launch (ordered before k2a by the launch boundary).
__global__ void __launch_bounds__(256, 2)
k1_node(const float* __restrict__ x,
        const float* __restrict__ Wfc,   const float* __restrict__ bfc,
        const float* __restrict__ Wself, const float* __restrict__ bself,
        const float* __restrict__ Wattn,
        float* __restrict__ out)
{
    extern __shared__ float sm[];
    float* sWfc = sm;                     // 128*64
    float* sWs  = sm + IND * OUTD;        // 128*64
    float* sx   = sm + 2 * IND * OUTD;    // 8 warps * 8 nodes * 128
    const int tid = threadIdx.x;

    {   // zero degree counters
        int gt = blockIdx.x * blockDim.x + tid;
        int gs = gridDim.x * blockDim.x;
        for (int i = gt; i < NN; i += gs) g_deg[i] = 0;
    }
    for (int i = tid; i < (IND * OUTD) / 4; i += blockDim.x) {
        ((float4*)sWfc)[i] = ((const float4*)Wfc)[i];
        ((float4*)sWs)[i]  = ((const float4*)Wself)[i];
    }
    __syncthreads();

    const int warp = tid >> 5, lane = tid & 31;
    const int gw = blockIdx.x * 8 + warp, nw = gridDim.x * 8;
    float* sxw = sx + warp * (8 * IND);

    const ull bfp = pack2f(((const float2*)bfc)[lane]);
    const ull bsp = pack2f(((const float2*)bself)[lane]);
    const float wa_s0 = Wattn[2 * lane],        wa_s1 = Wattn[2 * lane + 1];
    const float wa_d0 = Wattn[OUTD + 2 * lane], wa_d1 = Wattn[OUTD + 2 * lane + 1];

    for (int n0 = gw * 8; n0 < NN; n0 += nw * 8) {      // 50000 % 8 == 0
#pragma unroll
        for (int k = 0; k < 8; k++)
            ((float4*)(sxw + k * IND))[lane] =
                ((const float4*)(x + (size_t)(n0 + k) * IND))[lane];
        __syncwarp();

        ull aF[8], aS[8];
#pragma unroll
        for (int k = 0; k < 8; k++) { aF[k] = bfp; aS[k] = bsp; }

#pragma unroll 2
        for (int d2 = 0; d2 < IND / 2; d2++) {
            float2 xq[8];
#pragma unroll
            for (int k = 0; k < 8; k++)
                xq[k] = ((const float2*)(sxw + k * IND))[d2];   // broadcast LDS.64
#pragma unroll
            for (int dd = 0; dd < 2; dd++) {
                const int d = d2 * 2 + dd;
                ull wf = ((const ull*)(sWfc + d * OUTD))[lane];
                ull ws = ((const ull*)(sWs  + d * OUTD))[lane];
#pragma unroll
                for (int k = 0; k < 8; k++) {
                    ull xv = bcast2(dd == 0 ? xq[k].x : xq[k].y);
                    fma2(aF[k], xv, wf);
                    fma2(aS[k], xv, ws);
                }
            }
        }
#pragma unroll
        for (int k = 0; k < 8; k++) {
            float2 z = unpack2(aF[k]);
            ((float2*)(g_z + (size_t)(n0 + k) * OUTD))[lane] = z;
            ((float2*)(out + (size_t)(n0 + k) * OUTD))[lane] = unpack2(aS[k]);
            float ps = wredsum(z.x * wa_s0 + z.y * wa_s1);
            float pd = wredsum(z.x * wa_d0 + z.y * wa_d1);
            if (lane == 0) { g_asrc[n0 + k] = ps; g_adst[n0 + k] = pd; }
        }
        __syncwarp();
    }
}

// ---------------- K2a: in-degree count ----------------
__global__ void k2a_deg(const int* __restrict__ eidx)
{
    int e = blockIdx.x * blockDim.x + threadIdx.x;   // grid exact
    atomicAdd(&g_deg[__ldg(eidx + EE + e)], 1);
}

// ---------------- K2b: exclusive scan of degrees (single block) ----------------
__global__ void k2b_scan()
{
    __shared__ int swarp[32];
    const int tid = threadIdx.x, lane = tid & 31, w = tid >> 5;
    int carry = 0;
    for (int base = 0; base < NN; base += 1024) {
        int i = base + tid;
        int v = (i < NN) ? g_deg[i] : 0;
        int sv = v;
#pragma unroll
        for (int o = 1; o < 32; o <<= 1) {
            int t = __shfl_up_sync(0xffffffffu, sv, o);
            if (lane >= o) sv += t;
        }
        if (lane == 31) swarp[w] = sv;
        __syncthreads();
        if (w == 0) {
            int ws = swarp[lane];
#pragma unroll
            for (int o = 1; o < 32; o <<= 1) {
                int t = __shfl_up_sync(0xffffffffu, ws, o);
                if (lane >= o) ws += t;
            }
            swarp[lane] = ws;
        }
        __syncthreads();
        int excl = carry + (w > 0 ? swarp[w - 1] : 0) + sv - v;
        if (i < NN) { g_start[i] = excl; g_cursor[i] = excl; }
        int tot = swarp[31];
        __syncthreads();          // protect swarp before next iteration
        carry += tot;
    }
}

// ---------------- K2c: edge logits -> packed CSR records ----------------
// p = exp(leaky(a_src[row] + a_dst[col] + ea.Wa_e + b)); record {p,row,e} at
// the next free CSR slot of col. ONE atomic per edge (vs 97 RED lanes before).
__global__ void k2c_edge(const float* __restrict__ ea, const int* __restrict__ eidx,
                         const float* __restrict__ Wattn, const float* __restrict__ battn)
{
    int gt = blockIdx.x * blockDim.x + threadIdx.x;
    int e  = gt >> 3, sl = gt & 7;                    // grid exact: e < EE

    float4 ev = ((const float4*)(ea + (size_t)e * EDD))[sl];
    float4 w  = __ldg((const float4*)(Wattn + 2 * OUTD) + sl);
    float s = ev.x * w.x + ev.y * w.y + ev.z * w.z + ev.w * w.w;
    s += __shfl_xor_sync(0xffffffffu, s, 4);
    s += __shfl_xor_sync(0xffffffffu, s, 2);
    s += __shfl_xor_sync(0xffffffffu, s, 1);

    if (sl == 0) {
        int row = __ldg(eidx + e);
        int col = __ldg(eidx + EE + e);
        float logit = g_asrc[row] + g_adst[col] + s + battn[0];
        float lr = logit > 0.f ? logit : 0.2f * logit;
        float p  = __expf(lr);   // logits bounded ~|6|: max-shift elided, alpha unchanged
        int pos = atomicAdd(&g_cursor[col], 1);
        g_pack[pos] = make_float4(p, __int_as_float(row), __int_as_float(e), 0.f);
    }
}

// ---------------- K3: gather + full epilogue (one warp per dst node) ----------------
// accZ = sum p*z[row]; accG = sum p*ea[e]; den = sum p  -- register accumulation,
// zero atomics. Then out[n] += (accZ + accG@W_edge)/den + (deg>0 ? b_edge : 0).
__global__ void __launch_bounds__(256)
k3_gather(const float* __restrict__ ea, const float* __restrict__ We,
          const float* __restrict__ be, float* __restrict__ out)
{
    __shared__ __align__(16) float sWe[EDD * OUTD];
    __shared__ float sbe[OUTD];
    const int tid = threadIdx.x;
    for (int i = tid; i < (EDD * OUTD) / 4; i += blockDim.x)
        ((float4*)sWe)[i] = ((const float4*)We)[i];
    if (tid < OUTD) sbe[tid] = be[tid];
    __syncthreads();

    const int warp = tid >> 5, lane = tid & 31;
    const int n = blockIdx.x * 8 + warp;              // grid exact: n < NN
    const int start = g_start[n], deg = g_deg[n];
    const int jend = start + deg;

    ull accZ = 0;
    float accG = 0.f, den = 0.f;
    const float4* __restrict__ pk = g_pack;

#define GSTEP(P)                                                              \
    {   float p = (P).x;                                                      \
        int row = __float_as_int((P).y);                                      \
        int e   = __float_as_int((P).z);                                      \
        float2 z2 = ((const float2*)(g_z + (size_t)row * OUTD))[lane];        \
        float eav = __ldg(ea + (size_t)e * EDD + lane);                       \
        fma2(accZ, bcast2(p), pack2f(z2));                                    \
        accG = fmaf(p, eav, accG);                                            \
        den += p; }

    int j = start;
    for (; j + 4 <= jend; j += 4) {                   // 4 independent chains (MLP=4)
        float4 P0 = __ldg(pk + j);
        float4 P1 = __ldg(pk + j + 1);
        float4 P2 = __ldg(pk + j + 2);
        float4 P3 = __ldg(pk + j + 3);
        GSTEP(P0) GSTEP(P1) GSTEP(P2) GSTEP(P3)
    }
    for (; j < jend; j++) { float4 P = __ldg(pk + j); GSTEP(P) }
#undef GSTEP

    float inv = 1.f / fmaxf(den, 1e-16f);
    float g = accG * inv;                             // lane = edge-feature channel
    float acc0 = 0.f, acc1 = 0.f;
#pragma unroll
    for (int d = 0; d < EDD; d++) {
        float gd = __shfl_sync(0xffffffffu, g, d);
        float2 wv = ((const float2*)(sWe + d * OUTD))[lane];
        acc0 = fmaf(gd, wv.x, acc0);
        acc1 = fmaf(gd, wv.y, acc1);
    }
    float2 z = unpack2(accZ);
    float add0 = z.x * inv + acc0;
    float add1 = z.y * inv + acc1;
    if (deg > 0) { add0 += sbe[2 * lane]; add1 += sbe[2 * lane + 1]; }
    float2* op = (float2*)(out + (size_t)n * OUTD) + lane;
    float2 o = *op;
    o.x += add0; o.y += add1;
    *op = o;
}

// ---------------- launch ----------------
extern "C" void kernel_launch(void* const* d_in, const int* in_sizes, int n_in,
                              void* d_out, int out_size)
{
    const float* x     = (const float*)d_in[0];
    const float* ea    = (const float*)d_in[1];
    const int*   eidx  = (const int*)  d_in[2];
    const float* Wfc   = (const float*)d_in[3];
    const float* bfc   = (const float*)d_in[4];
    const float* Wattn = (const float*)d_in[5];
    const float* battn = (const float*)d_in[6];
    const float* Wedge = (const float*)d_in[7];
    const float* bedge = (const float*)d_in[8];
    const float* Wself = (const float*)d_in[9];
    const float* bself = (const float*)d_in[10];
    float* out = (float*)d_out;

    // weights 64KB + x staging 8 warps * 8 nodes * 128 floats = 32KB -> 96KB/block
    const size_t smem1 = (2 * IND * OUTD + 8 * 8 * IND) * sizeof(float);  // 98304 B
    cudaFuncSetAttribute(k1_node, cudaFuncAttributeMaxDynamicSharedMemorySize, (int)smem1);

    k1_node<<<296, 256, smem1>>>(x, Wfc, bfc, Wself, bself, Wattn, out);
    k2a_deg<<<EE / 256, 256>>>(eidx);                    // 3125 blocks, exact
    k2b_scan<<<1, 1024>>>();
    k2c_edge<<<(EE * 8) / 256, 256>>>(ea, eidx, Wattn, battn);   // 25000 blocks, exact
    k3_gather<<<(NN * 32) / 256, 256>>>(ea, Wedge, bedge, out);  // 6250 blocks, exact
}